// round 1
// baseline (speedup 1.0000x reference)
#include <cuda_runtime.h>
#include <math.h>

#define BATCHN 2
#define SEQ    2048
#define HID    2048
#define NH     16
#define HD     128
#define MROWS  (BATCHN*SEQ)   // 4096

// Scratch (device globals: allocation-free per harness rules)
__device__ float g_q [BATCHN*NH*SEQ*HD];
__device__ float g_k [BATCHN*NH*SEQ*HD];
__device__ float g_v [BATCHN*NH*SEQ*HD];
__device__ float g_ao[BATCHN*NH*SEQ*HD];
__device__ float g_cos[SEQ*(HD/2)];
__device__ float g_sin[SEQ*(HD/2)];

// ---------------------------------------------------------------------------
// RoPE table: fp64 trig so the angle matches the fp32 reference to <<1e-4
// ---------------------------------------------------------------------------
__global__ void rope_table_kernel()
{
    int idx = blockIdx.x * 256 + threadIdx.x;
    if (idx >= SEQ * (HD/2)) return;
    int s = idx >> 6;
    int d = idx & 63;
    double inv  = exp(-(double)d * (log(10000.0) / 64.0));
    double freq = (double)s * inv;
    g_cos[idx] = (float)cos(freq);
    g_sin[idx] = (float)sin(freq);
}

__global__ void rope_apply_kernel()
{
    int idx = blockIdx.x * 256 + threadIdx.x;   // over BATCHN*NH*SEQ*64
    if (idx >= BATCHN * NH * SEQ * (HD/2)) return;
    int d  = idx & 63;
    int s  = (idx >> 6) & (SEQ - 1);
    int bh = idx >> 17;
    float c  = g_cos[(s << 6) + d];
    float sn = g_sin[(s << 6) + d];
    int base = (bh * SEQ + s) * HD;

    float q1 = g_q[base + d], q2 = g_q[base + d + 64];
    g_q[base + d]      = q1 * c - q2 * sn;
    g_q[base + d + 64] = q2 * c + q1 * sn;

    float k1 = g_k[base + d], k2 = g_k[base + d + 64];
    g_k[base + d]      = k1 * c - k2 * sn;
    g_k[base + d + 64] = k2 * c + k1 * sn;
}

// ---------------------------------------------------------------------------
// SGEMM: C[m,n] = sum_k A[m,k] * W[n,k]   (both K-major, like torch Linear)
// MODE 0: A = x, z selects Wq/Wk/Wv, output remapped to [B,H,S,D] scratch
// MODE 1: A = attention output (read with [B,H,S,D]->[m,k] remap), C = d_out
// 128x128x16 tiles, 256 threads, 8x8 micro-tile.
// ---------------------------------------------------------------------------
#define GP 132   // smem pitch (multiple of 4 -> aligned float4 reads)

template<int MODE>
__global__ __launch_bounds__(256)
void gemm_kernel(const float* __restrict__ A,
                 const float* __restrict__ W0,
                 const float* __restrict__ W1,
                 const float* __restrict__ W2,
                 float* __restrict__ Cout)
{
    __shared__ float As[16 * GP];
    __shared__ float Bs[16 * GP];

    const int tid = threadIdx.x;
    const int tx  = tid & 15;
    const int ty  = tid >> 4;
    const int m0  = blockIdx.y * 128;
    const int n0  = blockIdx.x * 128;

    const float* W = W0;
    if (MODE == 0) {
        if (blockIdx.z == 1) W = W1;
        else if (blockIdx.z == 2) W = W2;
    }

    float acc[8][8];
    #pragma unroll
    for (int i = 0; i < 8; i++)
        #pragma unroll
        for (int j = 0; j < 8; j++) acc[i][j] = 0.f;

    for (int k0 = 0; k0 < HID; k0 += 16) {
        #pragma unroll
        for (int t = 0; t < 2; t++) {
            int idx = tid + t * 256;        // 0..511
            int row = idx >> 2;             // 0..127
            int k4  = (idx & 3) << 2;       // 0,4,8,12
            float4 av;
            if (MODE == 0) {
                av = *(const float4*)&A[(size_t)(m0 + row) * HID + k0 + k4];
            } else {
                int m  = m0 + row;
                int kk = k0 + k4;
                av = *(const float4*)&g_ao[((size_t)(((m >> 11) * NH) + (kk >> 7)) * SEQ
                                            + (m & 2047)) * HD + (kk & 127)];
            }
            float4 bv = *(const float4*)&W[(size_t)(n0 + row) * HID + k0 + k4];
            As[(k4+0)*GP + row] = av.x;  As[(k4+1)*GP + row] = av.y;
            As[(k4+2)*GP + row] = av.z;  As[(k4+3)*GP + row] = av.w;
            Bs[(k4+0)*GP + row] = bv.x;  Bs[(k4+1)*GP + row] = bv.y;
            Bs[(k4+2)*GP + row] = bv.z;  Bs[(k4+3)*GP + row] = bv.w;
        }
        __syncthreads();

        #pragma unroll
        for (int kk = 0; kk < 16; kk++) {
            float af[8], bf[8];
            *(float4*)&af[0] = *(float4*)&As[kk*GP + ty*4];
            *(float4*)&af[4] = *(float4*)&As[kk*GP + 64 + ty*4];
            *(float4*)&bf[0] = *(float4*)&Bs[kk*GP + tx*4];
            *(float4*)&bf[4] = *(float4*)&Bs[kk*GP + 64 + tx*4];
            #pragma unroll
            for (int i = 0; i < 8; i++)
                #pragma unroll
                for (int j = 0; j < 8; j++)
                    acc[i][j] += af[i] * bf[j];
        }
        __syncthreads();
    }

    #pragma unroll
    for (int i = 0; i < 8; i++) {
        int row = (i < 4) ? ty*4 + i : 64 + ty*4 + (i - 4);
        int m = m0 + row;
        #pragma unroll
        for (int j = 0; j < 8; j++) {
            int col = (j < 4) ? tx*4 + j : 64 + tx*4 + (j - 4);
            int n = n0 + col;
            if (MODE == 0) {
                float* dst = (blockIdx.z == 0) ? g_q : (blockIdx.z == 1) ? g_k : g_v;
                dst[((size_t)(((m >> 11) * NH) + (n >> 7)) * SEQ + (m & 2047)) * HD
                    + (n & 127)] = acc[i][j];
            } else {
                Cout[(size_t)m * HID + n] = acc[i][j];
            }
        }
    }
}

// ---------------------------------------------------------------------------
// Flash attention (causal), fp32. BM=128 q-rows, BN=64 kv-cols, D=128.
// 256 threads: S micro 8x4, O micro 8x8 (same row ownership).
// ---------------------------------------------------------------------------
#define QP 129
#define KP 129
#define VP 132
#define PP 65
#define FL_SMEM ((128*QP + 64*KP + 64*VP + 128*PP) * 4)   // 166144 B

__global__ __launch_bounds__(256, 1)
void flash_kernel()
{
    extern __shared__ float sm[];
    float* Qs = sm;                  // [128][QP]
    float* Ks = Qs + 128*QP;         // [64][KP]
    float* Vs = Ks + 64*KP;          // [64][VP]
    float* Ps = Vs + 64*VP;          // [128][PP]

    const int tid = threadIdx.x;
    const int tx  = tid & 15;
    const int ty  = tid >> 4;
    const int q0  = blockIdx.x * 128;
    const int bh  = blockIdx.y;

    const float* qg = g_q + (size_t)bh * SEQ * HD;
    const float* kg = g_k + (size_t)bh * SEQ * HD;
    const float* vg = g_v + (size_t)bh * SEQ * HD;

    int R[8];
    #pragma unroll
    for (int i = 0; i < 8; i++) R[i] = (i < 4) ? ty*4 + i : 64 + ty*4 + (i - 4);

    // Q tile -> smem (natural layout, odd pitch)
    #pragma unroll
    for (int it = 0; it < 16; it++) {
        int idx = tid + it * 256;
        int row = idx >> 5;
        int d4  = (idx & 31) << 2;
        float4 v = *(const float4*)&qg[(size_t)(q0 + row) * HD + d4];
        float* p = &Qs[row*QP + d4];
        p[0] = v.x; p[1] = v.y; p[2] = v.z; p[3] = v.w;
    }

    float o[8][8];
    float mrow[8], lrow[8];
    #pragma unroll
    for (int i = 0; i < 8; i++) {
        mrow[i] = -INFINITY;
        lrow[i] = 0.f;
        #pragma unroll
        for (int j = 0; j < 8; j++) o[i][j] = 0.f;
    }

    const float scale = 0.088388347648318447f;   // 1/sqrt(128)
    const int nkv = (q0 + 128) >> 6;             // causal tile bound

    for (int kvt = 0; kvt < nkv; kvt++) {
        int kv0 = kvt << 6;
        __syncthreads();   // Q-load done (first iter) / previous PV done

        #pragma unroll
        for (int it = 0; it < 8; it++) {
            int idx = tid + it * 256;
            int row = idx >> 5;
            int d4  = (idx & 31) << 2;
            float4 kvv = *(const float4*)&kg[(size_t)(kv0 + row) * HD + d4];
            float* p = &Ks[row*KP + d4];
            p[0] = kvv.x; p[1] = kvv.y; p[2] = kvv.z; p[3] = kvv.w;
            float4 vv = *(const float4*)&vg[(size_t)(kv0 + row) * HD + d4];
            *(float4*)&Vs[row*VP + d4] = vv;
        }
        __syncthreads();

        // S = Q K^T  (8 rows x 4 cols per thread)
        float s_acc[8][4];
        #pragma unroll
        for (int i = 0; i < 8; i++)
            #pragma unroll
            for (int j = 0; j < 4; j++) s_acc[i][j] = 0.f;

        #pragma unroll 4
        for (int k = 0; k < 128; k++) {
            float kf[4];
            #pragma unroll
            for (int j = 0; j < 4; j++) kf[j] = Ks[(tx*4 + j)*KP + k];
            #pragma unroll
            for (int i = 0; i < 8; i++) {
                float qv = Qs[R[i]*QP + k];
                #pragma unroll
                for (int j = 0; j < 4; j++) s_acc[i][j] += qv * kf[j];
            }
        }

        // mask + scale + online softmax (row group = 16 lanes sharing ty)
        #pragma unroll
        for (int i = 0; i < 8; i++) {
            int qrow = q0 + R[i];
            #pragma unroll
            for (int j = 0; j < 4; j++) {
                int kcol = kv0 + tx*4 + j;
                s_acc[i][j] = (kcol <= qrow) ? s_acc[i][j] * scale : -INFINITY;
            }
            float mx = fmaxf(fmaxf(s_acc[i][0], s_acc[i][1]),
                             fmaxf(s_acc[i][2], s_acc[i][3]));
            #pragma unroll
            for (int off = 8; off > 0; off >>= 1)
                mx = fmaxf(mx, __shfl_xor_sync(0xffffffffu, mx, off));
            float mnew = fmaxf(mrow[i], mx);
            float corr = __expf(mrow[i] - mnew);
            float psum = 0.f;
            #pragma unroll
            for (int j = 0; j < 4; j++) {
                float p = __expf(s_acc[i][j] - mnew);
                s_acc[i][j] = p;
                psum += p;
            }
            #pragma unroll
            for (int off = 8; off > 0; off >>= 1)
                psum += __shfl_xor_sync(0xffffffffu, psum, off);
            lrow[i] = lrow[i] * corr + psum;
            mrow[i] = mnew;
            #pragma unroll
            for (int j = 0; j < 8; j++) o[i][j] *= corr;
            #pragma unroll
            for (int j = 0; j < 4; j++) Ps[R[i]*PP + tx*4 + j] = s_acc[i][j];
        }
        __syncthreads();

        // O += P V  (8x8 per thread)
        #pragma unroll 2
        for (int kv = 0; kv < 64; kv++) {
            float4 va = *(const float4*)&Vs[kv*VP + tx*4];
            float4 vb = *(const float4*)&Vs[kv*VP + 64 + tx*4];
            float vf[8] = {va.x, va.y, va.z, va.w, vb.x, vb.y, vb.z, vb.w};
            #pragma unroll
            for (int i = 0; i < 8; i++) {
                float pv = Ps[R[i]*PP + kv];
                #pragma unroll
                for (int j = 0; j < 8; j++) o[i][j] += pv * vf[j];
            }
        }
    }

    // normalize + write [B,H,S,D]
    #pragma unroll
    for (int i = 0; i < 8; i++) {
        float inv = 1.f / lrow[i];
        int row = q0 + R[i];
        float* dst = g_ao + ((size_t)bh * SEQ + row) * HD;
        float4 a = make_float4(o[i][0]*inv, o[i][1]*inv, o[i][2]*inv, o[i][3]*inv);
        float4 b = make_float4(o[i][4]*inv, o[i][5]*inv, o[i][6]*inv, o[i][7]*inv);
        *(float4*)&dst[tx*4]      = a;
        *(float4*)&dst[64 + tx*4] = b;
    }
}

// ---------------------------------------------------------------------------
extern "C" void kernel_launch(void* const* d_in, const int* in_sizes, int n_in,
                              void* d_out, int out_size)
{
    const float* x  = (const float*)d_in[0];
    const float* Wq = (const float*)d_in[1];
    const float* Wk = (const float*)d_in[2];
    const float* Wv = (const float*)d_in[3];
    const float* Wo = (const float*)d_in[4];
    float* out = (float*)d_out;

    cudaFuncSetAttribute(flash_kernel,
                         cudaFuncAttributeMaxDynamicSharedMemorySize, FL_SMEM);

    rope_table_kernel<<<(SEQ*(HD/2) + 255)/256, 256>>>();
    gemm_kernel<0><<<dim3(HID/128, MROWS/128, 3), 256>>>(x, Wq, Wk, Wv, nullptr);
    rope_apply_kernel<<<(BATCHN*NH*SEQ*(HD/2) + 255)/256, 256>>>();
    flash_kernel<<<dim3(SEQ/128, BATCHN*NH), 256, FL_SMEM>>>();
    gemm_kernel<1><<<dim3(HID/128, MROWS/128, 1), 256>>>(nullptr, Wo, nullptr, nullptr, out);
}

// round 4
// speedup vs baseline: 1.5500x; 1.5500x over previous
#include <cuda_runtime.h>
#include <math.h>

#define BATCHN 2
#define SEQ    2048
#define HID    2048
#define NH     16
#define HD     128
#define MROWS  (BATCHN*SEQ)   // 4096

// ---------------------------------------------------------------------------
// Device scratch
// ---------------------------------------------------------------------------
__device__ __align__(16) float g_q [BATCHN*NH*SEQ*HD];
__device__ __align__(16) float g_k [BATCHN*NH*SEQ*HD];
__device__ __align__(16) float g_v [BATCHN*NH*SEQ*HD];
__device__ __align__(16) float g_ao[BATCHN*NH*SEQ*HD];
__device__ __align__(16) float g_cos[SEQ*(HD/2)];
__device__ __align__(16) float g_sin[SEQ*(HD/2)];
// tf32-rounded copies of inputs
__device__ __align__(16) float g_xc[MROWS*HID];
__device__ __align__(16) float g_wq[HID*HID];
__device__ __align__(16) float g_wk[HID*HID];
__device__ __align__(16) float g_wv[HID*HID];
__device__ __align__(16) float g_wo[HID*HID];

// ---------------------------------------------------------------------------
// Helpers
// ---------------------------------------------------------------------------
__device__ __forceinline__ void cpasync16(unsigned dst, const void* src) {
    asm volatile("cp.async.cg.shared.global [%0], [%1], 16;" :: "r"(dst), "l"(src));
}
#define CP_COMMIT() asm volatile("cp.async.commit_group;" ::: "memory")
#define CP_WAIT(n)  asm volatile("cp.async.wait_group %0;" :: "n"(n) : "memory")

__device__ __forceinline__ unsigned smem_u32(const void* p) {
    unsigned a;
    asm("{ .reg .u64 t; cvta.to.shared.u64 t, %1; cvt.u32.u64 %0, t; }"
        : "=r"(a) : "l"(p));
    return a;
}

__device__ __forceinline__ float tf32_round(float v) {
    return __uint_as_float(__float_as_uint(v) + 0x1000u);
}

// m16n8k8 tf32 mma: D = A*B + D (A row-major 16x8, B col-major 8x8)
__device__ __forceinline__ void mma_tf32(float* c, const unsigned* a, const unsigned* b) {
    asm volatile(
        "mma.sync.aligned.m16n8k8.row.col.f32.tf32.tf32.f32 "
        "{%0,%1,%2,%3}, {%4,%5,%6,%7}, {%8,%9}, {%0,%1,%2,%3};"
        : "+f"(c[0]), "+f"(c[1]), "+f"(c[2]), "+f"(c[3])
        : "r"(a[0]), "r"(a[1]), "r"(a[2]), "r"(a[3]), "r"(b[0]), "r"(b[1]));
}

// ---------------------------------------------------------------------------
// RoPE table (fp64 trig for accuracy)
// ---------------------------------------------------------------------------
__global__ void rope_table_kernel()
{
    int idx = blockIdx.x * 256 + threadIdx.x;
    if (idx >= SEQ * (HD/2)) return;
    int s = idx >> 6;
    int d = idx & 63;
    double inv  = exp(-(double)d * (log(10000.0) / 64.0));
    double freq = (double)s * inv;
    g_cos[idx] = (float)cos(freq);
    g_sin[idx] = (float)sin(freq);
}

__global__ void rope_apply_kernel()
{
    int idx = blockIdx.x * 256 + threadIdx.x;   // over BATCHN*NH*SEQ*64
    if (idx >= BATCHN * NH * SEQ * (HD/2)) return;
    int d  = idx & 63;
    int s  = (idx >> 6) & (SEQ - 1);
    int bh = idx >> 17;
    float c  = g_cos[(s << 6) + d];
    float sn = g_sin[(s << 6) + d];
    int base = (bh * SEQ + s) * HD;

    float q1 = g_q[base + d], q2 = g_q[base + d + 64];
    g_q[base + d]      = q1 * c - q2 * sn;
    g_q[base + d + 64] = q2 * c + q1 * sn;

    float k1 = g_k[base + d], k2 = g_k[base + d + 64];
    g_k[base + d]      = k1 * c - k2 * sn;
    g_k[base + d + 64] = k2 * c + k1 * sn;
}

// ---------------------------------------------------------------------------
// Round inputs to nearest tf32 (+0x1000; HMMA tf32 truncation completes it)
// ---------------------------------------------------------------------------
__global__ void convert_kernel(const float4* __restrict__ x,
                               const float4* __restrict__ wq,
                               const float4* __restrict__ wk,
                               const float4* __restrict__ wv,
                               const float4* __restrict__ wo)
{
    const int NX = (MROWS*HID)/4;
    const int NW = (HID*HID)/4;
    int i = blockIdx.x * 256 + threadIdx.x;
    const float4* src; float4* dst; int r;
    if (i < NX)                { src = x;  dst = (float4*)g_xc; r = i; }
    else if (i < NX + NW)      { src = wq; dst = (float4*)g_wq; r = i - NX; }
    else if (i < NX + 2*NW)    { src = wk; dst = (float4*)g_wk; r = i - NX - NW; }
    else if (i < NX + 3*NW)    { src = wv; dst = (float4*)g_wv; r = i - NX - 2*NW; }
    else if (i < NX + 4*NW)    { src = wo; dst = (float4*)g_wo; r = i - NX - 3*NW; }
    else return;
    float4 v = src[r];
    v.x = tf32_round(v.x); v.y = tf32_round(v.y);
    v.z = tf32_round(v.z); v.w = tf32_round(v.w);
    dst[r] = v;
}

// ---------------------------------------------------------------------------
// tf32 mma.sync GEMM:  C[m,n] = sum_k A[m,k] * W[n,k]
// MODE 0: A = g_xc, W in {g_wq,g_wk,g_wv} by z; out -> g_q/g_k/g_v [B,H,S,D]
// MODE 1: A = g_ao (read via [B,H,S,D] remap), W = g_wo, out -> Cout (d_out)
// CTA tile 128x128, K-chunk 32, 8 warps (4m x 2n), warp tile 32x64,
// double-buffered cp.async.
// ---------------------------------------------------------------------------
#define KC       32
#define NCHUNK   (HID/KC)          // 64
#define PITCH    36                // floats; 4*l4+lm mod 32 -> conflict-free
#define STG_FLT  (2*128*PITCH)     // A + B per stage = 9216 floats
#define GEMM_SMEM (2*STG_FLT*4)    // 73728 bytes

template<int MODE>
__global__ __launch_bounds__(256)
void gemm_mma(float* __restrict__ Cout)
{
    extern __shared__ float smemf[];
    const unsigned sbase = smem_u32(smemf);

    const int tid  = threadIdx.x;
    const int wid  = tid >> 5;
    const int lane = tid & 31;
    const int l4   = lane >> 2;
    const int lm   = lane & 3;
    const int wm   = wid & 3;        // 0..3 (m block of 32)
    const int wn   = wid >> 2;       // 0..1 (n block of 64)
    const int m0   = blockIdx.y * 128;
    const int n0   = blockIdx.x * 128;
    const int z    = (MODE == 0) ? blockIdx.z : 0;

    const float* Wsel;
    if (MODE == 0) Wsel = (z == 0) ? g_wq : (z == 1) ? g_wk : g_wv;
    else           Wsel = g_wo;

    // producer mapping: thread -> (row, 64B segment-group)
    const int prow = tid >> 1;          // 0..127
    const int pseg = (tid & 1) * 4;     // segment group: 4 x 16B

    const float* Bsrc = Wsel + (size_t)(n0 + prow) * HID + pseg * 4;
    const float* Asrc0;
    int b_ = 0, s_ = 0;
    if (MODE == 0) {
        Asrc0 = g_xc + (size_t)(m0 + prow) * HID + pseg * 4;
    } else {
        int m = m0 + prow;
        b_ = m >> 11; s_ = m & 2047;
        Asrc0 = nullptr;
    }

    float acc[2][8][4];
    #pragma unroll
    for (int mt = 0; mt < 2; mt++)
        #pragma unroll
        for (int nt = 0; nt < 8; nt++)
            #pragma unroll
            for (int q = 0; q < 4; q++) acc[mt][nt][q] = 0.f;

    // ---- stage loader ----
    auto load_stage = [&](int c, int buf) {
        const int k0 = c * KC;
        const unsigned sA = sbase + (unsigned)(buf * STG_FLT) * 4;
        const unsigned sB = sA + 128 * PITCH * 4;
        const float* Ap;
        if (MODE == 0) {
            Ap = Asrc0 + k0;
        } else {
            const int h = k0 >> 7;
            Ap = g_ao + ((size_t)(b_ * NH + h) * SEQ + s_) * HD + (k0 & 127) + pseg * 4;
        }
        const float* Bp = Bsrc + k0;
        #pragma unroll
        for (int i = 0; i < 4; i++) {
            cpasync16(sA + (unsigned)(prow * PITCH + (pseg + i) * 4) * 4, Ap + i * 4);
            cpasync16(sB + (unsigned)(prow * PITCH + (pseg + i) * 4) * 4, Bp + i * 4);
        }
        CP_COMMIT();
    };

    load_stage(0, 0);

    for (int c = 0; c < NCHUNK; c++) {
        const int buf = c & 1;
        if (c + 1 < NCHUNK) { load_stage(c + 1, buf ^ 1); CP_WAIT(1); }
        else                { CP_WAIT(0); }
        __syncthreads();

        const float* As  = smemf + buf * STG_FLT;
        const float* Bsm = As + 128 * PITCH;

        #pragma unroll
        for (int kk = 0; kk < 4; kk++) {
            const int kb = kk * 8;
            unsigned a[2][4], bfr[8][2];
            #pragma unroll
            for (int mt = 0; mt < 2; mt++) {
                const int r = wm * 32 + mt * 16 + l4;
                a[mt][0] = __float_as_uint(As[r * PITCH + kb + lm]);
                a[mt][1] = __float_as_uint(As[(r + 8) * PITCH + kb + lm]);
                a[mt][2] = __float_as_uint(As[r * PITCH + kb + lm + 4]);
                a[mt][3] = __float_as_uint(As[(r + 8) * PITCH + kb + lm + 4]);
            }
            #pragma unroll
            for (int nt = 0; nt < 8; nt++) {
                const int n = wn * 64 + nt * 8 + l4;
                bfr[nt][0] = __float_as_uint(Bsm[n * PITCH + kb + lm]);
                bfr[nt][1] = __float_as_uint(Bsm[n * PITCH + kb + lm + 4]);
            }
            #pragma unroll
            for (int mt = 0; mt < 2; mt++)
                #pragma unroll
                for (int nt = 0; nt < 8; nt++)
                    mma_tf32(acc[mt][nt], a[mt], bfr[nt]);
        }
        __syncthreads();
    }

    // ---- epilogue ----
    const int h = n0 >> 7;   // head (MODE 0): n tile == one head
    #pragma unroll
    for (int mt = 0; mt < 2; mt++) {
        #pragma unroll
        for (int half = 0; half < 2; half++) {
            const int row = m0 + wm * 32 + mt * 16 + l4 + half * 8;
            float* base;
            if (MODE == 0) {
                float* sel = (z == 0) ? g_q : (z == 1) ? g_k : g_v;
                base = sel + (((size_t)(row >> 11) * NH + h) * SEQ + (row & 2047)) * HD;
            } else {
                base = Cout + (size_t)row * HID + n0;
            }
            #pragma unroll
            for (int nt = 0; nt < 8; nt++) {
                const int d = wn * 64 + nt * 8 + 2 * lm;
                float2 v;
                v.x = acc[mt][nt][half * 2 + 0];
                v.y = acc[mt][nt][half * 2 + 1];
                *(float2*)&base[d] = v;
            }
        }
    }
}

// ---------------------------------------------------------------------------
// Flash attention (causal), fp32 SIMT (R1-proven), tf32-rounded g_ao output.
// ---------------------------------------------------------------------------
#define QP 129
#define KP 129
#define VP 132
#define PP 65
#define FL_SMEM ((128*QP + 64*KP + 64*VP + 128*PP) * 4)   // 166144 B

__global__ __launch_bounds__(256, 1)
void flash_kernel()
{
    extern __shared__ float sm[];
    float* Qs = sm;
    float* Ks = Qs + 128*QP;
    float* Vs = Ks + 64*KP;
    float* Ps = Vs + 64*VP;

    const int tid = threadIdx.x;
    const int tx  = tid & 15;
    const int ty  = tid >> 4;
    const int q0  = blockIdx.x * 128;
    const int bh  = blockIdx.y;

    const float* qg = g_q + (size_t)bh * SEQ * HD;
    const float* kg = g_k + (size_t)bh * SEQ * HD;
    const float* vg = g_v + (size_t)bh * SEQ * HD;

    int R[8];
    #pragma unroll
    for (int i = 0; i < 8; i++) R[i] = (i < 4) ? ty*4 + i : 64 + ty*4 + (i - 4);

    #pragma unroll
    for (int it = 0; it < 16; it++) {
        int idx = tid + it * 256;
        int row = idx >> 5;
        int d4  = (idx & 31) << 2;
        float4 v = *(const float4*)&qg[(size_t)(q0 + row) * HD + d4];
        float* p = &Qs[row*QP + d4];
        p[0] = v.x; p[1] = v.y; p[2] = v.z; p[3] = v.w;
    }

    float o[8][8];
    float mrow[8], lrow[8];
    #pragma unroll
    for (int i = 0; i < 8; i++) {
        mrow[i] = -INFINITY;
        lrow[i] = 0.f;
        #pragma unroll
        for (int j = 0; j < 8; j++) o[i][j] = 0.f;
    }

    const float scale = 0.088388347648318447f;
    const int nkv = (q0 + 128) >> 6;

    for (int kvt = 0; kvt < nkv; kvt++) {
        int kv0 = kvt << 6;
        __syncthreads();

        #pragma unroll
        for (int it = 0; it < 8; it++) {
            int idx = tid + it * 256;
            int row = idx >> 5;
            int d4  = (idx & 31) << 2;
            float4 kvv = *(const float4*)&kg[(size_t)(kv0 + row) * HD + d4];
            float* p = &Ks[row*KP + d4];
            p[0] = kvv.x; p[1] = kvv.y; p[2] = kvv.z; p[3] = kvv.w;
            float4 vv = *(const float4*)&vg[(size_t)(kv0 + row) * HD + d4];
            *(float4*)&Vs[row*VP + d4] = vv;
        }
        __syncthreads();

        float s_acc[8][4];
        #pragma unroll
        for (int i = 0; i < 8; i++)
            #pragma unroll
            for (int j = 0; j < 4; j++) s_acc[i][j] = 0.f;

        #pragma unroll 4
        for (int k = 0; k < 128; k++) {
            float kf[4];
            #pragma unroll
            for (int j = 0; j < 4; j++) kf[j] = Ks[(tx*4 + j)*KP + k];
            #pragma unroll
            for (int i = 0; i < 8; i++) {
                float qv = Qs[R[i]*QP + k];
                #pragma unroll
                for (int j = 0; j < 4; j++) s_acc[i][j] += qv * kf[j];
            }
        }

        #pragma unroll
        for (int i = 0; i < 8; i++) {
            int qrow = q0 + R[i];
            #pragma unroll
            for (int j = 0; j < 4; j++) {
                int kcol = kv0 + tx*4 + j;
                s_acc[i][j] = (kcol <= qrow) ? s_acc[i][j] * scale : -INFINITY;
            }
            float mx = fmaxf(fmaxf(s_acc[i][0], s_acc[i][1]),
                             fmaxf(s_acc[i][2], s_acc[i][3]));
            #pragma unroll
            for (int off = 8; off > 0; off >>= 1)
                mx = fmaxf(mx, __shfl_xor_sync(0xffffffffu, mx, off));
            float mnew = fmaxf(mrow[i], mx);
            float corr = __expf(mrow[i] - mnew);
            float psum = 0.f;
            #pragma unroll
            for (int j = 0; j < 4; j++) {
                float p = __expf(s_acc[i][j] - mnew);
                s_acc[i][j] = p;
                psum += p;
            }
            #pragma unroll
            for (int off = 8; off > 0; off >>= 1)
                psum += __shfl_xor_sync(0xffffffffu, psum, off);
            lrow[i] = lrow[i] * corr + psum;
            mrow[i] = mnew;
            #pragma unroll
            for (int j = 0; j < 8; j++) o[i][j] *= corr;
            #pragma unroll
            for (int j = 0; j < 4; j++) Ps[R[i]*PP + tx*4 + j] = s_acc[i][j];
        }
        __syncthreads();

        #pragma unroll 2
        for (int kv = 0; kv < 64; kv++) {
            float4 va = *(const float4*)&Vs[kv*VP + tx*4];
            float4 vb = *(const float4*)&Vs[kv*VP + 64 + tx*4];
            float vf[8] = {va.x, va.y, va.z, va.w, vb.x, vb.y, vb.z, vb.w};
            #pragma unroll
            for (int i = 0; i < 8; i++) {
                float pv = Ps[R[i]*PP + kv];
                #pragma unroll
                for (int j = 0; j < 8; j++) o[i][j] += pv * vf[j];
            }
        }
    }

    #pragma unroll
    for (int i = 0; i < 8; i++) {
        float inv = 1.f / lrow[i];
        int row = q0 + R[i];
        float* dst = g_ao + ((size_t)bh * SEQ + row) * HD;
        float4 a = make_float4(tf32_round(o[i][0]*inv), tf32_round(o[i][1]*inv),
                               tf32_round(o[i][2]*inv), tf32_round(o[i][3]*inv));
        float4 b = make_float4(tf32_round(o[i][4]*inv), tf32_round(o[i][5]*inv),
                               tf32_round(o[i][6]*inv), tf32_round(o[i][7]*inv));
        *(float4*)&dst[tx*4]      = a;
        *(float4*)&dst[64 + tx*4] = b;
    }
}

// ---------------------------------------------------------------------------
extern "C" void kernel_launch(void* const* d_in, const int* in_sizes, int n_in,
                              void* d_out, int out_size)
{
    const float4* x  = (const float4*)d_in[0];
    const float4* Wq = (const float4*)d_in[1];
    const float4* Wk = (const float4*)d_in[2];
    const float4* Wv = (const float4*)d_in[3];
    const float4* Wo = (const float4*)d_in[4];
    float* out = (float*)d_out;

    cudaFuncSetAttribute(flash_kernel,
                         cudaFuncAttributeMaxDynamicSharedMemorySize, FL_SMEM);
    cudaFuncSetAttribute(gemm_mma<0>,
                         cudaFuncAttributeMaxDynamicSharedMemorySize, GEMM_SMEM);
    cudaFuncSetAttribute(gemm_mma<1>,
                         cudaFuncAttributeMaxDynamicSharedMemorySize, GEMM_SMEM);

    rope_table_kernel<<<(SEQ*(HD/2) + 255)/256, 256>>>();

    const int NCV = (MROWS*HID)/4 + 4*((HID*HID)/4);
    convert_kernel<<<(NCV + 255)/256, 256>>>(x, Wq, Wk, Wv, Wo);

    gemm_mma<0><<<dim3(HID/128, MROWS/128, 3), 256, GEMM_SMEM>>>(nullptr);
    rope_apply_kernel<<<(BATCHN*NH*SEQ*(HD/2) + 255)/256, 256>>>();
    flash_kernel<<<dim3(SEQ/128, BATCHN*NH), 256, FL_SMEM>>>();
    gemm_mma<1><<<dim3(HID/128, MROWS/128, 1), 256, GEMM_SMEM>>>(out);
}

// round 10
// speedup vs baseline: 2.3473x; 1.5144x over previous
#include <cuda_runtime.h>
#include <math.h>

#define BATCHN 2
#define SEQ    2048
#define HID    2048
#define NH     16
#define HD     128
#define MROWS  (BATCHN*SEQ)   // 4096

// ---------------------------------------------------------------------------
// Device scratch
// ---------------------------------------------------------------------------
__device__ __align__(16) float g_q [BATCHN*NH*SEQ*HD];
__device__ __align__(16) float g_k [BATCHN*NH*SEQ*HD];
__device__ __align__(16) float g_v [BATCHN*NH*SEQ*HD];
__device__ __align__(16) float g_ao[BATCHN*NH*SEQ*HD];
__device__ __align__(16) float g_cos[SEQ*(HD/2)];
__device__ __align__(16) float g_sin[SEQ*(HD/2)];
// tf32-rounded copies of inputs
__device__ __align__(16) float g_xc[MROWS*HID];
__device__ __align__(16) float g_wq[HID*HID];
__device__ __align__(16) float g_wk[HID*HID];
__device__ __align__(16) float g_wv[HID*HID];
__device__ __align__(16) float g_wo[HID*HID];

// ---------------------------------------------------------------------------
// Helpers
// ---------------------------------------------------------------------------
__device__ __forceinline__ void cpasync16(unsigned dst, const void* src) {
    asm volatile("cp.async.cg.shared.global [%0], [%1], 16;" :: "r"(dst), "l"(src));
}
#define CP_COMMIT() asm volatile("cp.async.commit_group;" ::: "memory")
#define CP_WAIT(n)  asm volatile("cp.async.wait_group %0;" :: "n"(n) : "memory")

__device__ __forceinline__ unsigned smem_u32(const void* p) {
    unsigned a;
    asm("{ .reg .u64 t; cvta.to.shared.u64 t, %1; cvt.u32.u64 %0, t; }"
        : "=r"(a) : "l"(p));
    return a;
}

__device__ __forceinline__ float tf32_round(float v) {
    return __uint_as_float(__float_as_uint(v) + 0x1000u);
}

// m16n8k8 tf32 mma: D = A*B + D (A row-major 16x8, B col-major 8x8)
__device__ __forceinline__ void mma_tf32(float* c, const unsigned* a, const unsigned* b) {
    asm volatile(
        "mma.sync.aligned.m16n8k8.row.col.f32.tf32.tf32.f32 "
        "{%0,%1,%2,%3}, {%4,%5,%6,%7}, {%8,%9}, {%0,%1,%2,%3};"
        : "+f"(c[0]), "+f"(c[1]), "+f"(c[2]), "+f"(c[3])
        : "r"(a[0]), "r"(a[1]), "r"(a[2]), "r"(a[3]), "r"(b[0]), "r"(b[1]));
}

// ---------------------------------------------------------------------------
// RoPE table (fp64 trig for accuracy)
// ---------------------------------------------------------------------------
__global__ void rope_table_kernel()
{
    int idx = blockIdx.x * 256 + threadIdx.x;
    if (idx >= SEQ * (HD/2)) return;
    int s = idx >> 6;
    int d = idx & 63;
    double inv  = exp(-(double)d * (log(10000.0) / 64.0));
    double freq = (double)s * inv;
    g_cos[idx] = (float)cos(freq);
    g_sin[idx] = (float)sin(freq);
}

__global__ void rope_apply_kernel()
{
    int idx = blockIdx.x * 256 + threadIdx.x;   // over BATCHN*NH*SEQ*64
    if (idx >= BATCHN * NH * SEQ * (HD/2)) return;
    int d  = idx & 63;
    int s  = (idx >> 6) & (SEQ - 1);
    int bh = idx >> 17;
    float c  = g_cos[(s << 6) + d];
    float sn = g_sin[(s << 6) + d];
    int base = (bh * SEQ + s) * HD;

    float q1 = g_q[base + d], q2 = g_q[base + d + 64];
    g_q[base + d]      = q1 * c - q2 * sn;
    g_q[base + d + 64] = q2 * c + q1 * sn;

    float k1 = g_k[base + d], k2 = g_k[base + d + 64];
    g_k[base + d]      = k1 * c - k2 * sn;
    g_k[base + d + 64] = k2 * c + k1 * sn;
}

// ---------------------------------------------------------------------------
// Round inputs to nearest tf32 (+0x1000; HMMA tf32 truncation completes it)
// ---------------------------------------------------------------------------
__global__ void convert_kernel(const float4* __restrict__ x,
                               const float4* __restrict__ wq,
                               const float4* __restrict__ wk,
                               const float4* __restrict__ wv,
                               const float4* __restrict__ wo)
{
    const int NX = (MROWS*HID)/4;
    const int NW = (HID*HID)/4;
    int i = blockIdx.x * 256 + threadIdx.x;
    const float4* src; float4* dst; int r;
    if (i < NX)                { src = x;  dst = (float4*)g_xc; r = i; }
    else if (i < NX + NW)      { src = wq; dst = (float4*)g_wq; r = i - NX; }
    else if (i < NX + 2*NW)    { src = wk; dst = (float4*)g_wk; r = i - NX - NW; }
    else if (i < NX + 3*NW)    { src = wv; dst = (float4*)g_wv; r = i - NX - 2*NW; }
    else if (i < NX + 4*NW)    { src = wo; dst = (float4*)g_wo; r = i - NX - 3*NW; }
    else return;
    float4 v = src[r];
    v.x = tf32_round(v.x); v.y = tf32_round(v.y);
    v.z = tf32_round(v.z); v.w = tf32_round(v.w);
    dst[r] = v;
}

// ---------------------------------------------------------------------------
// tf32 mma.sync GEMM:  C[m,n] = sum_k A[m,k] * W[n,k]   (R4-proven)
// ---------------------------------------------------------------------------
#define KC       32
#define NCHUNK   (HID/KC)          // 64
#define PITCH    36
#define STG_FLT  (2*128*PITCH)
#define GEMM_SMEM (2*STG_FLT*4)    // 73728 bytes

template<int MODE>
__global__ __launch_bounds__(256)
void gemm_mma(float* __restrict__ Cout)
{
    extern __shared__ float smemf[];
    const unsigned sbase = smem_u32(smemf);

    const int tid  = threadIdx.x;
    const int wid  = tid >> 5;
    const int lane = tid & 31;
    const int l4   = lane >> 2;
    const int lm   = lane & 3;
    const int wm   = wid & 3;
    const int wn   = wid >> 2;
    const int m0   = blockIdx.y * 128;
    const int n0   = blockIdx.x * 128;
    const int z    = (MODE == 0) ? blockIdx.z : 0;

    const float* Wsel;
    if (MODE == 0) Wsel = (z == 0) ? g_wq : (z == 1) ? g_wk : g_wv;
    else           Wsel = g_wo;

    const int prow = tid >> 1;
    const int pseg = (tid & 1) * 4;

    const float* Bsrc = Wsel + (size_t)(n0 + prow) * HID + pseg * 4;
    const float* Asrc0;
    int b_ = 0, s_ = 0;
    if (MODE == 0) {
        Asrc0 = g_xc + (size_t)(m0 + prow) * HID + pseg * 4;
    } else {
        int m = m0 + prow;
        b_ = m >> 11; s_ = m & 2047;
        Asrc0 = nullptr;
    }

    float acc[2][8][4];
    #pragma unroll
    for (int mt = 0; mt < 2; mt++)
        #pragma unroll
        for (int nt = 0; nt < 8; nt++)
            #pragma unroll
            for (int q = 0; q < 4; q++) acc[mt][nt][q] = 0.f;

    auto load_stage = [&](int c, int buf) {
        const int k0 = c * KC;
        const unsigned sA = sbase + (unsigned)(buf * STG_FLT) * 4;
        const unsigned sB = sA + 128 * PITCH * 4;
        const float* Ap;
        if (MODE == 0) {
            Ap = Asrc0 + k0;
        } else {
            const int h = k0 >> 7;
            Ap = g_ao + ((size_t)(b_ * NH + h) * SEQ + s_) * HD + (k0 & 127) + pseg * 4;
        }
        const float* Bp = Bsrc + k0;
        #pragma unroll
        for (int i = 0; i < 4; i++) {
            cpasync16(sA + (unsigned)(prow * PITCH + (pseg + i) * 4) * 4, Ap + i * 4);
            cpasync16(sB + (unsigned)(prow * PITCH + (pseg + i) * 4) * 4, Bp + i * 4);
        }
        CP_COMMIT();
    };

    load_stage(0, 0);

    for (int c = 0; c < NCHUNK; c++) {
        const int buf = c & 1;
        if (c + 1 < NCHUNK) { load_stage(c + 1, buf ^ 1); CP_WAIT(1); }
        else                { CP_WAIT(0); }
        __syncthreads();

        const float* As  = smemf + buf * STG_FLT;
        const float* Bsm = As + 128 * PITCH;

        #pragma unroll
        for (int kk = 0; kk < 4; kk++) {
            const int kb = kk * 8;
            unsigned a[2][4], bfr[8][2];
            #pragma unroll
            for (int mt = 0; mt < 2; mt++) {
                const int r = wm * 32 + mt * 16 + l4;
                a[mt][0] = __float_as_uint(As[r * PITCH + kb + lm]);
                a[mt][1] = __float_as_uint(As[(r + 8) * PITCH + kb + lm]);
                a[mt][2] = __float_as_uint(As[r * PITCH + kb + lm + 4]);
                a[mt][3] = __float_as_uint(As[(r + 8) * PITCH + kb + lm + 4]);
            }
            #pragma unroll
            for (int nt = 0; nt < 8; nt++) {
                const int n = wn * 64 + nt * 8 + l4;
                bfr[nt][0] = __float_as_uint(Bsm[n * PITCH + kb + lm]);
                bfr[nt][1] = __float_as_uint(Bsm[n * PITCH + kb + lm + 4]);
            }
            #pragma unroll
            for (int mt = 0; mt < 2; mt++)
                #pragma unroll
                for (int nt = 0; nt < 8; nt++)
                    mma_tf32(acc[mt][nt], a[mt], bfr[nt]);
        }
        __syncthreads();
    }

    const int h = n0 >> 7;
    #pragma unroll
    for (int mt = 0; mt < 2; mt++) {
        #pragma unroll
        for (int half = 0; half < 2; half++) {
            const int row = m0 + wm * 32 + mt * 16 + l4 + half * 8;
            float* base;
            if (MODE == 0) {
                float* sel = (z == 0) ? g_q : (z == 1) ? g_k : g_v;
                base = sel + (((size_t)(row >> 11) * NH + h) * SEQ + (row & 2047)) * HD;
            } else {
                base = Cout + (size_t)row * HID + n0;
            }
            #pragma unroll
            for (int nt = 0; nt < 8; nt++) {
                const int d = wn * 64 + nt * 8 + 2 * lm;
                float2 v;
                v.x = acc[mt][nt][half * 2 + 0];
                v.y = acc[mt][nt][half * 2 + 1];
                *(float2*)&base[d] = v;
            }
        }
    }
}

// ---------------------------------------------------------------------------
// Flash attention (causal) with mma.sync tf32.
// BM=128 q-rows, BN=64 kv, 8 warps; warp owns 16 q-rows (softmax warp-local).
// S phase: warp 16x64 (8 n-tiles x 16 ksteps). PV: warp 16x128 (16 n-tiles).
// ---------------------------------------------------------------------------
#define FQP 132
#define FKP 132
#define FVP 136
#define FPP 68
#define FL_SMEM ((128*FQP + 64*FKP + 64*FVP + 128*FPP) * 4)   // 171008 B

__global__ __launch_bounds__(256, 1)
void flash_mma_kernel()
{
    extern __shared__ float sm[];
    float* Qs = sm;                  // [128][FQP]
    float* Ks = Qs + 128*FQP;        // [64][FKP]
    float* Vs = Ks + 64*FKP;         // [64][FVP]
    float* Ps = Vs + 64*FVP;         // [128][FPP]

    const int tid  = threadIdx.x;
    const int wid  = tid >> 5;       // 0..7 -> q-row block of 16
    const int lane = tid & 31;
    const int l4   = lane >> 2;
    const int lm   = lane & 3;
    const int q0   = blockIdx.x * 128;
    const int bh   = blockIdx.y;

    const float* qg = g_q + (size_t)bh * SEQ * HD;
    const float* kg = g_k + (size_t)bh * SEQ * HD;
    const float* vg = g_v + (size_t)bh * SEQ * HD;

    const float scale = 0.088388347648318447f;   // 1/sqrt(128)

    // Q -> smem, pre-scaled and tf32-rounded
    #pragma unroll
    for (int it = 0; it < 16; it++) {
        int idx = tid + it * 256;
        int row = idx >> 5;
        int d4  = (idx & 31) << 2;
        float4 v = *(const float4*)&qg[(size_t)(q0 + row) * HD + d4];
        float* p = &Qs[row*FQP + d4];
        p[0] = tf32_round(v.x * scale); p[1] = tf32_round(v.y * scale);
        p[2] = tf32_round(v.z * scale); p[3] = tf32_round(v.w * scale);
    }

    float o[16][4];
    #pragma unroll
    for (int nt = 0; nt < 16; nt++)
        #pragma unroll
        for (int q = 0; q < 4; q++) o[nt][q] = 0.f;
    float mrow[2] = {-INFINITY, -INFINITY};
    float lrow[2] = {0.f, 0.f};

    const int rbase = wid * 16 + l4;       // thread's row (half 0); +8 for half 1
    const int nkv   = (q0 + 128) >> 6;

    for (int kvt = 0; kvt < nkv; kvt++) {
        const int kv0 = kvt << 6;
        __syncthreads();   // Ks/Vs safe to overwrite

        // K,V tiles -> smem (tf32-rounded)
        #pragma unroll
        for (int it = 0; it < 8; it++) {
            int idx = tid + it * 256;
            int row = idx >> 5;
            int d4  = (idx & 31) << 2;
            float4 kv4 = *(const float4*)&kg[(size_t)(kv0 + row) * HD + d4];
            float* pk = &Ks[row*FKP + d4];
            pk[0] = tf32_round(kv4.x); pk[1] = tf32_round(kv4.y);
            pk[2] = tf32_round(kv4.z); pk[3] = tf32_round(kv4.w);
            float4 vv = *(const float4*)&vg[(size_t)(kv0 + row) * HD + d4];
            float* pv = &Vs[row*FVP + d4];
            pv[0] = tf32_round(vv.x); pv[1] = tf32_round(vv.y);
            pv[2] = tf32_round(vv.z); pv[3] = tf32_round(vv.w);
        }
        __syncthreads();

        // ---- S = Q K^T (pre-scaled) ----
        float s[8][4];
        #pragma unroll
        for (int nt = 0; nt < 8; nt++)
            #pragma unroll
            for (int q = 0; q < 4; q++) s[nt][q] = 0.f;

        #pragma unroll
        for (int ks = 0; ks < 16; ks++) {
            const int kb = ks * 8;
            unsigned a[4];
            a[0] = __float_as_uint(Qs[(rbase    )*FQP + kb + lm]);
            a[1] = __float_as_uint(Qs[(rbase + 8)*FQP + kb + lm]);
            a[2] = __float_as_uint(Qs[(rbase    )*FQP + kb + lm + 4]);
            a[3] = __float_as_uint(Qs[(rbase + 8)*FQP + kb + lm + 4]);
            #pragma unroll
            for (int nt = 0; nt < 8; nt++) {
                unsigned b[2];
                b[0] = __float_as_uint(Ks[(nt*8 + l4)*FKP + kb + lm]);
                b[1] = __float_as_uint(Ks[(nt*8 + l4)*FKP + kb + lm + 4]);
                mma_tf32(s[nt], a, b);
            }
        }

        // ---- mask + online softmax (rows warp-local; reduce over lm lanes) ----
        const bool need_mask = (kv0 + 63 > q0 + wid*16);
        #pragma unroll
        for (int half = 0; half < 2; half++) {
            const int row = q0 + rbase + half * 8;
            float mx = -INFINITY;
            #pragma unroll
            for (int nt = 0; nt < 8; nt++) {
                #pragma unroll
                for (int j = 0; j < 2; j++) {
                    float val = s[nt][half*2 + j];
                    if (need_mask) {
                        int col = kv0 + nt*8 + 2*lm + j;
                        if (col > row) val = -INFINITY;
                    }
                    s[nt][half*2 + j] = val;
                    mx = fmaxf(mx, val);
                }
            }
            mx = fmaxf(mx, __shfl_xor_sync(0xffffffffu, mx, 1));
            mx = fmaxf(mx, __shfl_xor_sync(0xffffffffu, mx, 2));
            const float mnew = fmaxf(mrow[half], mx);
            const float corr = __expf(mrow[half] - mnew);
            float psum = 0.f;
            #pragma unroll
            for (int nt = 0; nt < 8; nt++) {
                float p0 = __expf(s[nt][half*2 + 0] - mnew);
                float p1 = __expf(s[nt][half*2 + 1] - mnew);
                s[nt][half*2 + 0] = p0;
                s[nt][half*2 + 1] = p1;
                psum += p0 + p1;
            }
            psum += __shfl_xor_sync(0xffffffffu, psum, 1);
            psum += __shfl_xor_sync(0xffffffffu, psum, 2);
            lrow[half] = lrow[half] * corr + psum;
            mrow[half] = mnew;
            #pragma unroll
            for (int nt = 0; nt < 16; nt++) {
                o[nt][half*2 + 0] *= corr;
                o[nt][half*2 + 1] *= corr;
            }
            // P -> smem (tf32-rounded), own rows only
            #pragma unroll
            for (int nt = 0; nt < 8; nt++) {
                float2 pv;
                pv.x = tf32_round(s[nt][half*2 + 0]);
                pv.y = tf32_round(s[nt][half*2 + 1]);
                *(float2*)&Ps[(rbase + half*8)*FPP + nt*8 + 2*lm] = pv;
            }
        }
        __syncwarp();   // P written/read only within this warp's 16 rows

        // ---- O += P V ----
        #pragma unroll
        for (int ks = 0; ks < 8; ks++) {
            unsigned a[4];
            a[0] = __float_as_uint(Ps[(rbase    )*FPP + ks*8 + lm]);
            a[1] = __float_as_uint(Ps[(rbase + 8)*FPP + ks*8 + lm]);
            a[2] = __float_as_uint(Ps[(rbase    )*FPP + ks*8 + lm + 4]);
            a[3] = __float_as_uint(Ps[(rbase + 8)*FPP + ks*8 + lm + 4]);
            #pragma unroll
            for (int nt = 0; nt < 16; nt++) {
                unsigned b[2];
                b[0] = __float_as_uint(Vs[(ks*8 + lm    )*FVP + nt*8 + l4]);
                b[1] = __float_as_uint(Vs[(ks*8 + lm + 4)*FVP + nt*8 + l4]);
                mma_tf32(o[nt], a, b);
            }
        }
    }

    // ---- normalize + write (tf32-rounded for the Wo GEMM) ----
    #pragma unroll
    for (int half = 0; half < 2; half++) {
        const float inv = 1.f / lrow[half];
        const int row = q0 + rbase + half * 8;
        float* dst = g_ao + ((size_t)bh * SEQ + row) * HD;
        #pragma unroll
        for (int nt = 0; nt < 16; nt++) {
            float2 v;
            v.x = tf32_round(o[nt][half*2 + 0] * inv);
            v.y = tf32_round(o[nt][half*2 + 1] * inv);
            *(float2*)&dst[nt*8 + 2*lm] = v;
        }
    }
}

// ---------------------------------------------------------------------------
extern "C" void kernel_launch(void* const* d_in, const int* in_sizes, int n_in,
                              void* d_out, int out_size)
{
    const float4* x  = (const float4*)d_in[0];
    const float4* Wq = (const float4*)d_in[1];
    const float4* Wk = (const float4*)d_in[2];
    const float4* Wv = (const float4*)d_in[3];
    const float4* Wo = (const float4*)d_in[4];
    float* out = (float*)d_out;

    cudaFuncSetAttribute(flash_mma_kernel,
                         cudaFuncAttributeMaxDynamicSharedMemorySize, FL_SMEM);
    cudaFuncSetAttribute(gemm_mma<0>,
                         cudaFuncAttributeMaxDynamicSharedMemorySize, GEMM_SMEM);
    cudaFuncSetAttribute(gemm_mma<1>,
                         cudaFuncAttributeMaxDynamicSharedMemorySize, GEMM_SMEM);

    rope_table_kernel<<<(SEQ*(HD/2) + 255)/256, 256>>>();

    const int NCV = (MROWS*HID)/4 + 4*((HID*HID)/4);
    convert_kernel<<<(NCV + 255)/256, 256>>>(x, Wq, Wk, Wv, Wo);

    gemm_mma<0><<<dim3(HID/128, MROWS/128, 3), 256, GEMM_SMEM>>>(nullptr);
    rope_apply_kernel<<<(BATCHN*NH*SEQ*(HD/2) + 255)/256, 256>>>();
    flash_mma_kernel<<<dim3(SEQ/128, BATCHN*NH), 256, FL_SMEM>>>();
    gemm_mma<1><<<dim3(HID/128, MROWS/128, 1), 256, GEMM_SMEM>>>(out);
}

// round 11
// speedup vs baseline: 2.4145x; 1.0286x over previous
#include <cuda_runtime.h>
#include <math.h>

#define BATCHN 2
#define SEQ    2048
#define HID    2048
#define NH     16
#define HD     128
#define MROWS  (BATCHN*SEQ)   // 4096

// ---------------------------------------------------------------------------
// Device scratch
// ---------------------------------------------------------------------------
__device__ __align__(16) float g_q [BATCHN*NH*SEQ*HD];
__device__ __align__(16) float g_k [BATCHN*NH*SEQ*HD];
__device__ __align__(16) float g_v [BATCHN*NH*SEQ*HD];
__device__ __align__(16) float g_ao[BATCHN*NH*SEQ*HD];
__device__ __align__(16) float g_cos[SEQ*(HD/2)];
__device__ __align__(16) float g_sin[SEQ*(HD/2)];
// tf32-rounded copies of inputs
__device__ __align__(16) float g_xc[MROWS*HID];
__device__ __align__(16) float g_wq[HID*HID];
__device__ __align__(16) float g_wk[HID*HID];
__device__ __align__(16) float g_wv[HID*HID];
__device__ __align__(16) float g_wo[HID*HID];

// ---------------------------------------------------------------------------
// Helpers
// ---------------------------------------------------------------------------
__device__ __forceinline__ void cpasync16(unsigned dst, const void* src) {
    asm volatile("cp.async.cg.shared.global [%0], [%1], 16;" :: "r"(dst), "l"(src));
}
#define CP_COMMIT() asm volatile("cp.async.commit_group;" ::: "memory")
#define CP_WAIT(n)  asm volatile("cp.async.wait_group %0;" :: "n"(n) : "memory")

__device__ __forceinline__ unsigned smem_u32(const void* p) {
    unsigned a;
    asm("{ .reg .u64 t; cvta.to.shared.u64 t, %1; cvt.u32.u64 %0, t; }"
        : "=r"(a) : "l"(p));
    return a;
}

__device__ __forceinline__ float tf32_round(float v) {
    return __uint_as_float(__float_as_uint(v) + 0x1000u);
}

// m16n8k8 tf32 mma: D = A*B + D (A row-major 16x8, B col-major 8x8)
__device__ __forceinline__ void mma_tf32(float* c, const unsigned* a, const unsigned* b) {
    asm volatile(
        "mma.sync.aligned.m16n8k8.row.col.f32.tf32.tf32.f32 "
        "{%0,%1,%2,%3}, {%4,%5,%6,%7}, {%8,%9}, {%0,%1,%2,%3};"
        : "+f"(c[0]), "+f"(c[1]), "+f"(c[2]), "+f"(c[3])
        : "r"(a[0]), "r"(a[1]), "r"(a[2]), "r"(a[3]), "r"(b[0]), "r"(b[1]));
}

// ---------------------------------------------------------------------------
// RoPE table (fp64 trig for accuracy)
// ---------------------------------------------------------------------------
__global__ void rope_table_kernel()
{
    int idx = blockIdx.x * 256 + threadIdx.x;
    if (idx >= SEQ * (HD/2)) return;
    int s = idx >> 6;
    int d = idx & 63;
    double inv  = exp(-(double)d * (log(10000.0) / 64.0));
    double freq = (double)s * inv;
    g_cos[idx] = (float)cos(freq);
    g_sin[idx] = (float)sin(freq);
}

__global__ void rope_apply_kernel()
{
    int idx = blockIdx.x * 256 + threadIdx.x;   // over BATCHN*NH*SEQ*64
    if (idx >= BATCHN * NH * SEQ * (HD/2)) return;
    int d  = idx & 63;
    int s  = (idx >> 6) & (SEQ - 1);
    int bh = idx >> 17;
    float c  = g_cos[(s << 6) + d];
    float sn = g_sin[(s << 6) + d];
    int base = (bh * SEQ + s) * HD;

    float q1 = g_q[base + d], q2 = g_q[base + d + 64];
    g_q[base + d]      = q1 * c - q2 * sn;
    g_q[base + d + 64] = q2 * c + q1 * sn;

    float k1 = g_k[base + d], k2 = g_k[base + d + 64];
    g_k[base + d]      = k1 * c - k2 * sn;
    g_k[base + d + 64] = k2 * c + k1 * sn;
}

// ---------------------------------------------------------------------------
// Round inputs to nearest tf32 (+0x1000; HMMA tf32 truncation completes it)
// ---------------------------------------------------------------------------
__global__ void convert_kernel(const float4* __restrict__ x,
                               const float4* __restrict__ wq,
                               const float4* __restrict__ wk,
                               const float4* __restrict__ wv,
                               const float4* __restrict__ wo)
{
    const int NX = (MROWS*HID)/4;
    const int NW = (HID*HID)/4;
    int i = blockIdx.x * 256 + threadIdx.x;
    const float4* src; float4* dst; int r;
    if (i < NX)                { src = x;  dst = (float4*)g_xc; r = i; }
    else if (i < NX + NW)      { src = wq; dst = (float4*)g_wq; r = i - NX; }
    else if (i < NX + 2*NW)    { src = wk; dst = (float4*)g_wk; r = i - NX - NW; }
    else if (i < NX + 3*NW)    { src = wv; dst = (float4*)g_wv; r = i - NX - 2*NW; }
    else if (i < NX + 4*NW)    { src = wo; dst = (float4*)g_wo; r = i - NX - 3*NW; }
    else return;
    float4 v = src[r];
    v.x = tf32_round(v.x); v.y = tf32_round(v.y);
    v.z = tf32_round(v.z); v.w = tf32_round(v.w);
    dst[r] = v;
}

// ---------------------------------------------------------------------------
// tf32 mma.sync GEMM:  C[m,n] = sum_k A[m,k] * W[n,k]
// R11 change: __launch_bounds__(256, 2) -> 2 CTAs/SM (latency hiding).
// ---------------------------------------------------------------------------
#define KC       32
#define NCHUNK   (HID/KC)          // 64
#define PITCH    36
#define STG_FLT  (2*128*PITCH)
#define GEMM_SMEM (2*STG_FLT*4)    // 73728 bytes

template<int MODE>
__global__ __launch_bounds__(256, 2)
void gemm_mma(float* __restrict__ Cout)
{
    extern __shared__ float smemf[];
    const unsigned sbase = smem_u32(smemf);

    const int tid  = threadIdx.x;
    const int wid  = tid >> 5;
    const int lane = tid & 31;
    const int l4   = lane >> 2;
    const int lm   = lane & 3;
    const int wm   = wid & 3;
    const int wn   = wid >> 2;
    const int m0   = blockIdx.y * 128;
    const int n0   = blockIdx.x * 128;
    const int z    = (MODE == 0) ? blockIdx.z : 0;

    const float* Wsel;
    if (MODE == 0) Wsel = (z == 0) ? g_wq : (z == 1) ? g_wk : g_wv;
    else           Wsel = g_wo;

    const int prow = tid >> 1;
    const int pseg = (tid & 1) * 4;

    const float* Bsrc = Wsel + (size_t)(n0 + prow) * HID + pseg * 4;
    const float* Asrc0;
    int b_ = 0, s_ = 0;
    if (MODE == 0) {
        Asrc0 = g_xc + (size_t)(m0 + prow) * HID + pseg * 4;
    } else {
        int m = m0 + prow;
        b_ = m >> 11; s_ = m & 2047;
        Asrc0 = nullptr;
    }

    float acc[2][8][4];
    #pragma unroll
    for (int mt = 0; mt < 2; mt++)
        #pragma unroll
        for (int nt = 0; nt < 8; nt++)
            #pragma unroll
            for (int q = 0; q < 4; q++) acc[mt][nt][q] = 0.f;

    auto load_stage = [&](int c, int buf) {
        const int k0 = c * KC;
        const unsigned sA = sbase + (unsigned)(buf * STG_FLT) * 4;
        const unsigned sB = sA + 128 * PITCH * 4;
        const float* Ap;
        if (MODE == 0) {
            Ap = Asrc0 + k0;
        } else {
            const int h = k0 >> 7;
            Ap = g_ao + ((size_t)(b_ * NH + h) * SEQ + s_) * HD + (k0 & 127) + pseg * 4;
        }
        const float* Bp = Bsrc + k0;
        #pragma unroll
        for (int i = 0; i < 4; i++) {
            cpasync16(sA + (unsigned)(prow * PITCH + (pseg + i) * 4) * 4, Ap + i * 4);
            cpasync16(sB + (unsigned)(prow * PITCH + (pseg + i) * 4) * 4, Bp + i * 4);
        }
        CP_COMMIT();
    };

    load_stage(0, 0);

    for (int c = 0; c < NCHUNK; c++) {
        const int buf = c & 1;
        if (c + 1 < NCHUNK) { load_stage(c + 1, buf ^ 1); CP_WAIT(1); }
        else                { CP_WAIT(0); }
        __syncthreads();

        const float* As  = smemf + buf * STG_FLT;
        const float* Bsm = As + 128 * PITCH;

        #pragma unroll
        for (int kk = 0; kk < 4; kk++) {
            const int kb = kk * 8;
            unsigned a[2][4], bfr[8][2];
            #pragma unroll
            for (int mt = 0; mt < 2; mt++) {
                const int r = wm * 32 + mt * 16 + l4;
                a[mt][0] = __float_as_uint(As[r * PITCH + kb + lm]);
                a[mt][1] = __float_as_uint(As[(r + 8) * PITCH + kb + lm]);
                a[mt][2] = __float_as_uint(As[r * PITCH + kb + lm + 4]);
                a[mt][3] = __float_as_uint(As[(r + 8) * PITCH + kb + lm + 4]);
            }
            #pragma unroll
            for (int nt = 0; nt < 8; nt++) {
                const int n = wn * 64 + nt * 8 + l4;
                bfr[nt][0] = __float_as_uint(Bsm[n * PITCH + kb + lm]);
                bfr[nt][1] = __float_as_uint(Bsm[n * PITCH + kb + lm + 4]);
            }
            #pragma unroll
            for (int mt = 0; mt < 2; mt++)
                #pragma unroll
                for (int nt = 0; nt < 8; nt++)
                    mma_tf32(acc[mt][nt], a[mt], bfr[nt]);
        }
        __syncthreads();
    }

    const int h = n0 >> 7;
    #pragma unroll
    for (int mt = 0; mt < 2; mt++) {
        #pragma unroll
        for (int half = 0; half < 2; half++) {
            const int row = m0 + wm * 32 + mt * 16 + l4 + half * 8;
            float* base;
            if (MODE == 0) {
                float* sel = (z == 0) ? g_q : (z == 1) ? g_k : g_v;
                base = sel + (((size_t)(row >> 11) * NH + h) * SEQ + (row & 2047)) * HD;
            } else {
                base = Cout + (size_t)row * HID + n0;
            }
            #pragma unroll
            for (int nt = 0; nt < 8; nt++) {
                const int d = wn * 64 + nt * 8 + 2 * lm;
                float2 v;
                v.x = acc[mt][nt][half * 2 + 0];
                v.y = acc[mt][nt][half * 2 + 1];
                *(float2*)&base[d] = v;
            }
        }
    }
}

// ---------------------------------------------------------------------------
// Flash attention (causal) with mma.sync tf32.  (R10-proven)
// BM=128 q-rows, BN=64 kv, 8 warps; warp owns 16 q-rows (softmax warp-local).
// ---------------------------------------------------------------------------
#define FQP 132
#define FKP 132
#define FVP 136
#define FPP 68
#define FL_SMEM ((128*FQP + 64*FKP + 64*FVP + 128*FPP) * 4)   // 171008 B

__global__ __launch_bounds__(256, 1)
void flash_mma_kernel()
{
    extern __shared__ float sm[];
    float* Qs = sm;                  // [128][FQP]
    float* Ks = Qs + 128*FQP;        // [64][FKP]
    float* Vs = Ks + 64*FKP;         // [64][FVP]
    float* Ps = Vs + 64*FVP;         // [128][FPP]

    const int tid  = threadIdx.x;
    const int wid  = tid >> 5;       // 0..7 -> q-row block of 16
    const int lane = tid & 31;
    const int l4   = lane >> 2;
    const int lm   = lane & 3;
    const int q0   = blockIdx.x * 128;
    const int bh   = blockIdx.y;

    const float* qg = g_q + (size_t)bh * SEQ * HD;
    const float* kg = g_k + (size_t)bh * SEQ * HD;
    const float* vg = g_v + (size_t)bh * SEQ * HD;

    const float scale = 0.088388347648318447f;   // 1/sqrt(128)

    // Q -> smem, pre-scaled and tf32-rounded
    #pragma unroll
    for (int it = 0; it < 16; it++) {
        int idx = tid + it * 256;
        int row = idx >> 5;
        int d4  = (idx & 31) << 2;
        float4 v = *(const float4*)&qg[(size_t)(q0 + row) * HD + d4];
        float* p = &Qs[row*FQP + d4];
        p[0] = tf32_round(v.x * scale); p[1] = tf32_round(v.y * scale);
        p[2] = tf32_round(v.z * scale); p[3] = tf32_round(v.w * scale);
    }

    float o[16][4];
    #pragma unroll
    for (int nt = 0; nt < 16; nt++)
        #pragma unroll
        for (int q = 0; q < 4; q++) o[nt][q] = 0.f;
    float mrow[2] = {-INFINITY, -INFINITY};
    float lrow[2] = {0.f, 0.f};

    const int rbase = wid * 16 + l4;       // thread's row (half 0); +8 for half 1
    const int nkv   = (q0 + 128) >> 6;

    for (int kvt = 0; kvt < nkv; kvt++) {
        const int kv0 = kvt << 6;
        __syncthreads();   // Ks/Vs safe to overwrite

        // K,V tiles -> smem (tf32-rounded)
        #pragma unroll
        for (int it = 0; it < 8; it++) {
            int idx = tid + it * 256;
            int row = idx >> 5;
            int d4  = (idx & 31) << 2;
            float4 kv4 = *(const float4*)&kg[(size_t)(kv0 + row) * HD + d4];
            float* pk = &Ks[row*FKP + d4];
            pk[0] = tf32_round(kv4.x); pk[1] = tf32_round(kv4.y);
            pk[2] = tf32_round(kv4.z); pk[3] = tf32_round(kv4.w);
            float4 vv = *(const float4*)&vg[(size_t)(kv0 + row) * HD + d4];
            float* pv = &Vs[row*FVP + d4];
            pv[0] = tf32_round(vv.x); pv[1] = tf32_round(vv.y);
            pv[2] = tf32_round(vv.z); pv[3] = tf32_round(vv.w);
        }
        __syncthreads();

        // ---- S = Q K^T (pre-scaled) ----
        float s[8][4];
        #pragma unroll
        for (int nt = 0; nt < 8; nt++)
            #pragma unroll
            for (int q = 0; q < 4; q++) s[nt][q] = 0.f;

        #pragma unroll
        for (int ks = 0; ks < 16; ks++) {
            const int kb = ks * 8;
            unsigned a[4];
            a[0] = __float_as_uint(Qs[(rbase    )*FQP + kb + lm]);
            a[1] = __float_as_uint(Qs[(rbase + 8)*FQP + kb + lm]);
            a[2] = __float_as_uint(Qs[(rbase    )*FQP + kb + lm + 4]);
            a[3] = __float_as_uint(Qs[(rbase + 8)*FQP + kb + lm + 4]);
            #pragma unroll
            for (int nt = 0; nt < 8; nt++) {
                unsigned b[2];
                b[0] = __float_as_uint(Ks[(nt*8 + l4)*FKP + kb + lm]);
                b[1] = __float_as_uint(Ks[(nt*8 + l4)*FKP + kb + lm + 4]);
                mma_tf32(s[nt], a, b);
            }
        }

        // ---- mask + online softmax (rows warp-local; reduce over lm lanes) ----
        const bool need_mask = (kv0 + 63 > q0 + wid*16);
        #pragma unroll
        for (int half = 0; half < 2; half++) {
            const int row = q0 + rbase + half * 8;
            float mx = -INFINITY;
            #pragma unroll
            for (int nt = 0; nt < 8; nt++) {
                #pragma unroll
                for (int j = 0; j < 2; j++) {
                    float val = s[nt][half*2 + j];
                    if (need_mask) {
                        int col = kv0 + nt*8 + 2*lm + j;
                        if (col > row) val = -INFINITY;
                    }
                    s[nt][half*2 + j] = val;
                    mx = fmaxf(mx, val);
                }
            }
            mx = fmaxf(mx, __shfl_xor_sync(0xffffffffu, mx, 1));
            mx = fmaxf(mx, __shfl_xor_sync(0xffffffffu, mx, 2));
            const float mnew = fmaxf(mrow[half], mx);
            const float corr = __expf(mrow[half] - mnew);
            float psum = 0.f;
            #pragma unroll
            for (int nt = 0; nt < 8; nt++) {
                float p0 = __expf(s[nt][half*2 + 0] - mnew);
                float p1 = __expf(s[nt][half*2 + 1] - mnew);
                s[nt][half*2 + 0] = p0;
                s[nt][half*2 + 1] = p1;
                psum += p0 + p1;
            }
            psum += __shfl_xor_sync(0xffffffffu, psum, 1);
            psum += __shfl_xor_sync(0xffffffffu, psum, 2);
            lrow[half] = lrow[half] * corr + psum;
            mrow[half] = mnew;
            #pragma unroll
            for (int nt = 0; nt < 16; nt++) {
                o[nt][half*2 + 0] *= corr;
                o[nt][half*2 + 1] *= corr;
            }
            // P -> smem (tf32-rounded), own rows only
            #pragma unroll
            for (int nt = 0; nt < 8; nt++) {
                float2 pv;
                pv.x = tf32_round(s[nt][half*2 + 0]);
                pv.y = tf32_round(s[nt][half*2 + 1]);
                *(float2*)&Ps[(rbase + half*8)*FPP + nt*8 + 2*lm] = pv;
            }
        }
        __syncwarp();   // P written/read only within this warp's 16 rows

        // ---- O += P V ----
        #pragma unroll
        for (int ks = 0; ks < 8; ks++) {
            unsigned a[4];
            a[0] = __float_as_uint(Ps[(rbase    )*FPP + ks*8 + lm]);
            a[1] = __float_as_uint(Ps[(rbase + 8)*FPP + ks*8 + lm]);
            a[2] = __float_as_uint(Ps[(rbase    )*FPP + ks*8 + lm + 4]);
            a[3] = __float_as_uint(Ps[(rbase + 8)*FPP + ks*8 + lm + 4]);
            #pragma unroll
            for (int nt = 0; nt < 16; nt++) {
                unsigned b[2];
                b[0] = __float_as_uint(Vs[(ks*8 + lm    )*FVP + nt*8 + l4]);
                b[1] = __float_as_uint(Vs[(ks*8 + lm + 4)*FVP + nt*8 + l4]);
                mma_tf32(o[nt], a, b);
            }
        }
    }

    // ---- normalize + write (tf32-rounded for the Wo GEMM) ----
    #pragma unroll
    for (int half = 0; half < 2; half++) {
        const float inv = 1.f / lrow[half];
        const int row = q0 + rbase + half * 8;
        float* dst = g_ao + ((size_t)bh * SEQ + row) * HD;
        #pragma unroll
        for (int nt = 0; nt < 16; nt++) {
            float2 v;
            v.x = tf32_round(o[nt][half*2 + 0] * inv);
            v.y = tf32_round(o[nt][half*2 + 1] * inv);
            *(float2*)&dst[nt*8 + 2*lm] = v;
        }
    }
}

// ---------------------------------------------------------------------------
extern "C" void kernel_launch(void* const* d_in, const int* in_sizes, int n_in,
                              void* d_out, int out_size)
{
    const float4* x  = (const float4*)d_in[0];
    const float4* Wq = (const float4*)d_in[1];
    const float4* Wk = (const float4*)d_in[2];
    const float4* Wv = (const float4*)d_in[3];
    const float4* Wo = (const float4*)d_in[4];
    float* out = (float*)d_out;

    cudaFuncSetAttribute(flash_mma_kernel,
                         cudaFuncAttributeMaxDynamicSharedMemorySize, FL_SMEM);
    cudaFuncSetAttribute(gemm_mma<0>,
                         cudaFuncAttributeMaxDynamicSharedMemorySize, GEMM_SMEM);
    cudaFuncSetAttribute(gemm_mma<1>,
                         cudaFuncAttributeMaxDynamicSharedMemorySize, GEMM_SMEM);

    rope_table_kernel<<<(SEQ*(HD/2) + 255)/256, 256>>>();

    const int NCV = (MROWS*HID)/4 + 4*((HID*HID)/4);
    convert_kernel<<<(NCV + 255)/256, 256>>>(x, Wq, Wk, Wv, Wo);

    gemm_mma<0><<<dim3(HID/128, MROWS/128, 3), 256, GEMM_SMEM>>>(nullptr);
    rope_apply_kernel<<<(BATCHN*NH*SEQ*(HD/2) + 255)/256, 256>>>();
    flash_mma_kernel<<<dim3(SEQ/128, BATCHN*NH), 256, FL_SMEM>>>();
    gemm_mma<1><<<dim3(HID/128, MROWS/128, 1), 256, GEMM_SMEM>>>(out);
}

// round 16
// speedup vs baseline: 4.0200x; 1.6649x over previous
#include <cuda_runtime.h>
#include <cuda_fp16.h>
#include <math.h>

#define BATCHN 2
#define SEQ    2048
#define HID    2048
#define NH     16
#define HD     128
#define MROWS  (BATCHN*SEQ)   // 4096

// ---------------------------------------------------------------------------
// Device scratch
// ---------------------------------------------------------------------------
__device__ __align__(16) float  g_q [BATCHN*NH*SEQ*HD];
__device__ __align__(16) float  g_k [BATCHN*NH*SEQ*HD];
__device__ __align__(16) float  g_v [BATCHN*NH*SEQ*HD];
__device__ __align__(16) __half g_ao[BATCHN*NH*SEQ*HD];   // fp16 for Wo GEMM
__device__ __align__(16) float  g_cos[SEQ*(HD/2)];
__device__ __align__(16) float  g_sin[SEQ*(HD/2)];
// fp16 copies of GEMM inputs
__device__ __align__(16) __half g_xh [MROWS*HID];
__device__ __align__(16) __half g_wqh[HID*HID];
__device__ __align__(16) __half g_wkh[HID*HID];
__device__ __align__(16) __half g_wvh[HID*HID];
__device__ __align__(16) __half g_woh[HID*HID];

// ---------------------------------------------------------------------------
// Helpers
// ---------------------------------------------------------------------------
__device__ __forceinline__ void cpasync16(unsigned dst, const void* src) {
    asm volatile("cp.async.cg.shared.global [%0], [%1], 16;" :: "r"(dst), "l"(src));
}
#define CP_COMMIT() asm volatile("cp.async.commit_group;" ::: "memory")
#define CP_WAIT(n)  asm volatile("cp.async.wait_group %0;" :: "n"(n) : "memory")

__device__ __forceinline__ unsigned smem_u32(const void* p) {
    unsigned a;
    asm("{ .reg .u64 t; cvta.to.shared.u64 t, %1; cvt.u32.u64 %0, t; }"
        : "=r"(a) : "l"(p));
    return a;
}

__device__ __forceinline__ float tf32_round(float v) {
    return __uint_as_float(__float_as_uint(v) + 0x1000u);
}

// m16n8k8 tf32 mma (flash kernel)
__device__ __forceinline__ void mma_tf32(float* c, const unsigned* a, const unsigned* b) {
    asm volatile(
        "mma.sync.aligned.m16n8k8.row.col.f32.tf32.tf32.f32 "
        "{%0,%1,%2,%3}, {%4,%5,%6,%7}, {%8,%9}, {%0,%1,%2,%3};"
        : "+f"(c[0]), "+f"(c[1]), "+f"(c[2]), "+f"(c[3])
        : "r"(a[0]), "r"(a[1]), "r"(a[2]), "r"(a[3]), "r"(b[0]), "r"(b[1]));
}

// m16n8k16 fp16 mma, f32 accumulate (projection GEMMs)
__device__ __forceinline__ void mma_f16(float* c, const unsigned* a, const unsigned* b) {
    asm volatile(
        "mma.sync.aligned.m16n8k16.row.col.f32.f16.f16.f32 "
        "{%0,%1,%2,%3}, {%4,%5,%6,%7}, {%8,%9}, {%0,%1,%2,%3};"
        : "+f"(c[0]), "+f"(c[1]), "+f"(c[2]), "+f"(c[3])
        : "r"(a[0]), "r"(a[1]), "r"(a[2]), "r"(a[3]), "r"(b[0]), "r"(b[1]));
}

// ---------------------------------------------------------------------------
// RoPE table (fp64 trig for accuracy)
// ---------------------------------------------------------------------------
__global__ void rope_table_kernel()
{
    int idx = blockIdx.x * 256 + threadIdx.x;
    if (idx >= SEQ * (HD/2)) return;
    int s = idx >> 6;
    int d = idx & 63;
    double inv  = exp(-(double)d * (log(10000.0) / 64.0));
    double freq = (double)s * inv;
    g_cos[idx] = (float)cos(freq);
    g_sin[idx] = (float)sin(freq);
}

__global__ void rope_apply_kernel()
{
    int idx = blockIdx.x * 256 + threadIdx.x;   // over BATCHN*NH*SEQ*64
    if (idx >= BATCHN * NH * SEQ * (HD/2)) return;
    int d  = idx & 63;
    int s  = (idx >> 6) & (SEQ - 1);
    int bh = idx >> 17;
    float c  = g_cos[(s << 6) + d];
    float sn = g_sin[(s << 6) + d];
    int base = (bh * SEQ + s) * HD;

    float q1 = g_q[base + d], q2 = g_q[base + d + 64];
    g_q[base + d]      = q1 * c - q2 * sn;
    g_q[base + d + 64] = q2 * c + q1 * sn;

    float k1 = g_k[base + d], k2 = g_k[base + d + 64];
    g_k[base + d]      = k1 * c - k2 * sn;
    g_k[base + d + 64] = k2 * c + k1 * sn;
}

// ---------------------------------------------------------------------------
// fp32 -> fp16 input conversion (split into two launches so gemm<0> lands in
// the profiler's sampled slot)
// ---------------------------------------------------------------------------
__global__ void convert_x_kernel(const float4* __restrict__ x)
{
    int i = blockIdx.x * 256 + threadIdx.x;
    if (i >= (MROWS*HID)/4) return;
    float4 v = x[i];
    __half2* dst = (__half2*)g_xh;
    dst[2*i]     = __floats2half2_rn(v.x, v.y);
    dst[2*i + 1] = __floats2half2_rn(v.z, v.w);
}

__global__ void convert_w_kernel(const float4* __restrict__ wq,
                                 const float4* __restrict__ wk,
                                 const float4* __restrict__ wv,
                                 const float4* __restrict__ wo)
{
    const int NW = (HID*HID)/4;
    int i = blockIdx.x * 256 + threadIdx.x;
    const float4* src; __half2* dst; int r;
    if (i < NW)            { src = wq; dst = (__half2*)g_wqh; r = i; }
    else if (i < 2*NW)     { src = wk; dst = (__half2*)g_wkh; r = i - NW; }
    else if (i < 3*NW)     { src = wv; dst = (__half2*)g_wvh; r = i - 2*NW; }
    else if (i < 4*NW)     { src = wo; dst = (__half2*)g_woh; r = i - 3*NW; }
    else return;
    float4 v = src[r];
    dst[2*r]     = __floats2half2_rn(v.x, v.y);
    dst[2*r + 1] = __floats2half2_rn(v.z, v.w);
}

// ---------------------------------------------------------------------------
// fp16 mma.sync GEMM:  C[m,n] = sum_k A[m,k] * W[n,k]   (f32 accumulate)
// CTA 128x128, K-chunk 32 halves (2 x k16 mma steps), 8 warps (4m x 2n),
// warp tile 32x64, double-buffered cp.async.  PITCH_H=40 halves: word index
// = 20*l4 + lm mod 32 -> conflict-free half2 fragment loads.
// ---------------------------------------------------------------------------
#define KC        32
#define NCHUNK    (HID/KC)          // 64
#define PITCH_H   40                // halves per row (80 bytes)
#define MAT_BYTES (128*PITCH_H*2)   // 10240
#define STG_BYTES (2*MAT_BYTES)     // 20480
#define GEMM_SMEM (2*STG_BYTES)     // 40960

template<int MODE>
__global__ __launch_bounds__(256, 2)
void gemm_mma(float* __restrict__ Cout)
{
    extern __shared__ char smem[];
    const unsigned sbase = smem_u32(smem);

    const int tid  = threadIdx.x;
    const int wid  = tid >> 5;
    const int lane = tid & 31;
    const int l4   = lane >> 2;
    const int lm   = lane & 3;
    const int wm   = wid & 3;
    const int wn   = wid >> 2;
    const int m0   = blockIdx.y * 128;
    const int n0   = blockIdx.x * 128;
    const int z    = (MODE == 0) ? blockIdx.z : 0;

    const __half* Wsel;
    if (MODE == 0) Wsel = (z == 0) ? g_wqh : (z == 1) ? g_wkh : g_wvh;
    else           Wsel = g_woh;

    const int prow = tid >> 1;          // 0..127
    const int pseg = (tid & 1) * 2;     // segment pair {pseg, pseg+1} of 4

    int b_ = 0, s_ = 0;
    if (MODE == 1) {
        int m = m0 + prow;
        b_ = m >> 11; s_ = m & 2047;
    }

    float acc[2][8][4];
    #pragma unroll
    for (int mt = 0; mt < 2; mt++)
        #pragma unroll
        for (int nt = 0; nt < 8; nt++)
            #pragma unroll
            for (int q = 0; q < 4; q++) acc[mt][nt][q] = 0.f;

    auto load_stage = [&](int c, int buf) {
        const int k0 = c * KC;
        const unsigned sA = sbase + (unsigned)buf * STG_BYTES;
        const unsigned sB = sA + MAT_BYTES;
        const __half* Ap;
        if (MODE == 0) {
            Ap = g_xh + (size_t)(m0 + prow) * HID + k0;
        } else {
            const int h = k0 >> 7;
            Ap = g_ao + ((size_t)(b_ * NH + h) * SEQ + s_) * HD + (k0 & 127);
        }
        const __half* Bp = Wsel + (size_t)(n0 + prow) * HID + k0;
        #pragma unroll
        for (int i = 0; i < 2; i++) {
            int seg = pseg + i;
            cpasync16(sA + (unsigned)(prow * 80 + seg * 16), Ap + seg * 8);
            cpasync16(sB + (unsigned)(prow * 80 + seg * 16), Bp + seg * 8);
        }
        CP_COMMIT();
    };

    load_stage(0, 0);

    for (int c = 0; c < NCHUNK; c++) {
        const int buf = c & 1;
        if (c + 1 < NCHUNK) { load_stage(c + 1, buf ^ 1); CP_WAIT(1); }
        else                { CP_WAIT(0); }
        __syncthreads();

        const __half* As = (const __half*)(smem + buf * STG_BYTES);
        const __half* Bs = As + 128 * PITCH_H;

        #pragma unroll
        for (int kk = 0; kk < 2; kk++) {
            const int kb = kk * 16;
            unsigned a[2][4], bfr[8][2];
            #pragma unroll
            for (int mt = 0; mt < 2; mt++) {
                const int r = wm * 32 + mt * 16 + l4;
                a[mt][0] = *(const unsigned*)&As[r * PITCH_H + kb + 2*lm];
                a[mt][1] = *(const unsigned*)&As[(r + 8) * PITCH_H + kb + 2*lm];
                a[mt][2] = *(const unsigned*)&As[r * PITCH_H + kb + 2*lm + 8];
                a[mt][3] = *(const unsigned*)&As[(r + 8) * PITCH_H + kb + 2*lm + 8];
            }
            #pragma unroll
            for (int nt = 0; nt < 8; nt++) {
                const int n = wn * 64 + nt * 8 + l4;
                bfr[nt][0] = *(const unsigned*)&Bs[n * PITCH_H + kb + 2*lm];
                bfr[nt][1] = *(const unsigned*)&Bs[n * PITCH_H + kb + 2*lm + 8];
            }
            #pragma unroll
            for (int mt = 0; mt < 2; mt++)
                #pragma unroll
                for (int nt = 0; nt < 8; nt++)
                    mma_f16(acc[mt][nt], a[mt], bfr[nt]);
        }
        __syncthreads();
    }

    const int h = n0 >> 7;
    #pragma unroll
    for (int mt = 0; mt < 2; mt++) {
        #pragma unroll
        for (int half = 0; half < 2; half++) {
            const int row = m0 + wm * 32 + mt * 16 + l4 + half * 8;
            float* base;
            if (MODE == 0) {
                float* sel = (z == 0) ? g_q : (z == 1) ? g_k : g_v;
                base = sel + (((size_t)(row >> 11) * NH + h) * SEQ + (row & 2047)) * HD;
            } else {
                base = Cout + (size_t)row * HID + n0;
            }
            #pragma unroll
            for (int nt = 0; nt < 8; nt++) {
                const int d = wn * 64 + nt * 8 + 2 * lm;
                float2 v;
                v.x = acc[mt][nt][half * 2 + 0];
                v.y = acc[mt][nt][half * 2 + 1];
                *(float2*)&base[d] = v;
            }
        }
    }
}

// ---------------------------------------------------------------------------
// Flash attention (causal) with mma.sync tf32.  (R10-proven core)
// Epilogue now writes g_ao as fp16 for the Wo GEMM.
// ---------------------------------------------------------------------------
#define FQP 132
#define FKP 132
#define FVP 136
#define FPP 68
#define FL_SMEM ((128*FQP + 64*FKP + 64*FVP + 128*FPP) * 4)   // 171008 B

__global__ __launch_bounds__(256, 1)
void flash_mma_kernel()
{
    extern __shared__ float sm[];
    float* Qs = sm;                  // [128][FQP]
    float* Ks = Qs + 128*FQP;        // [64][FKP]
    float* Vs = Ks + 64*FKP;         // [64][FVP]
    float* Ps = Vs + 64*FVP;         // [128][FPP]

    const int tid  = threadIdx.x;
    const int wid  = tid >> 5;       // 0..7 -> q-row block of 16
    const int lane = tid & 31;
    const int l4   = lane >> 2;
    const int lm   = lane & 3;
    const int q0   = blockIdx.x * 128;
    const int bh   = blockIdx.y;

    const float* qg = g_q + (size_t)bh * SEQ * HD;
    const float* kg = g_k + (size_t)bh * SEQ * HD;
    const float* vg = g_v + (size_t)bh * SEQ * HD;

    const float scale = 0.088388347648318447f;   // 1/sqrt(128)

    // Q -> smem, pre-scaled and tf32-rounded
    #pragma unroll
    for (int it = 0; it < 16; it++) {
        int idx = tid + it * 256;
        int row = idx >> 5;
        int d4  = (idx & 31) << 2;
        float4 v = *(const float4*)&qg[(size_t)(q0 + row) * HD + d4];
        float* p = &Qs[row*FQP + d4];
        p[0] = tf32_round(v.x * scale); p[1] = tf32_round(v.y * scale);
        p[2] = tf32_round(v.z * scale); p[3] = tf32_round(v.w * scale);
    }

    float o[16][4];
    #pragma unroll
    for (int nt = 0; nt < 16; nt++)
        #pragma unroll
        for (int q = 0; q < 4; q++) o[nt][q] = 0.f;
    float mrow[2] = {-INFINITY, -INFINITY};
    float lrow[2] = {0.f, 0.f};

    const int rbase = wid * 16 + l4;       // thread's row (half 0); +8 for half 1
    const int nkv   = (q0 + 128) >> 6;

    for (int kvt = 0; kvt < nkv; kvt++) {
        const int kv0 = kvt << 6;
        __syncthreads();   // Ks/Vs safe to overwrite

        // K,V tiles -> smem (tf32-rounded)
        #pragma unroll
        for (int it = 0; it < 8; it++) {
            int idx = tid + it * 256;
            int row = idx >> 5;
            int d4  = (idx & 31) << 2;
            float4 kv4 = *(const float4*)&kg[(size_t)(kv0 + row) * HD + d4];
            float* pk = &Ks[row*FKP + d4];
            pk[0] = tf32_round(kv4.x); pk[1] = tf32_round(kv4.y);
            pk[2] = tf32_round(kv4.z); pk[3] = tf32_round(kv4.w);
            float4 vv = *(const float4*)&vg[(size_t)(kv0 + row) * HD + d4];
            float* pv = &Vs[row*FVP + d4];
            pv[0] = tf32_round(vv.x); pv[1] = tf32_round(vv.y);
            pv[2] = tf32_round(vv.z); pv[3] = tf32_round(vv.w);
        }
        __syncthreads();

        // ---- S = Q K^T (pre-scaled) ----
        float s[8][4];
        #pragma unroll
        for (int nt = 0; nt < 8; nt++)
            #pragma unroll
            for (int q = 0; q < 4; q++) s[nt][q] = 0.f;

        #pragma unroll
        for (int ks = 0; ks < 16; ks++) {
            const int kb = ks * 8;
            unsigned a[4];
            a[0] = __float_as_uint(Qs[(rbase    )*FQP + kb + lm]);
            a[1] = __float_as_uint(Qs[(rbase + 8)*FQP + kb + lm]);
            a[2] = __float_as_uint(Qs[(rbase    )*FQP + kb + lm + 4]);
            a[3] = __float_as_uint(Qs[(rbase + 8)*FQP + kb + lm + 4]);
            #pragma unroll
            for (int nt = 0; nt < 8; nt++) {
                unsigned b[2];
                b[0] = __float_as_uint(Ks[(nt*8 + l4)*FKP + kb + lm]);
                b[1] = __float_as_uint(Ks[(nt*8 + l4)*FKP + kb + lm + 4]);
                mma_tf32(s[nt], a, b);
            }
        }

        // ---- mask + online softmax (rows warp-local; reduce over lm lanes) ----
        const bool need_mask = (kv0 + 63 > q0 + wid*16);
        #pragma unroll
        for (int half = 0; half < 2; half++) {
            const int row = q0 + rbase + half * 8;
            float mx = -INFINITY;
            #pragma unroll
            for (int nt = 0; nt < 8; nt++) {
                #pragma unroll
                for (int j = 0; j < 2; j++) {
                    float val = s[nt][half*2 + j];
                    if (need_mask) {
                        int col = kv0 + nt*8 + 2*lm + j;
                        if (col > row) val = -INFINITY;
                    }
                    s[nt][half*2 + j] = val;
                    mx = fmaxf(mx, val);
                }
            }
            mx = fmaxf(mx, __shfl_xor_sync(0xffffffffu, mx, 1));
            mx = fmaxf(mx, __shfl_xor_sync(0xffffffffu, mx, 2));
            const float mnew = fmaxf(mrow[half], mx);
            const float corr = __expf(mrow[half] - mnew);
            float psum = 0.f;
            #pragma unroll
            for (int nt = 0; nt < 8; nt++) {
                float p0 = __expf(s[nt][half*2 + 0] - mnew);
                float p1 = __expf(s[nt][half*2 + 1] - mnew);
                s[nt][half*2 + 0] = p0;
                s[nt][half*2 + 1] = p1;
                psum += p0 + p1;
            }
            psum += __shfl_xor_sync(0xffffffffu, psum, 1);
            psum += __shfl_xor_sync(0xffffffffu, psum, 2);
            lrow[half] = lrow[half] * corr + psum;
            mrow[half] = mnew;
            #pragma unroll
            for (int nt = 0; nt < 16; nt++) {
                o[nt][half*2 + 0] *= corr;
                o[nt][half*2 + 1] *= corr;
            }
            // P -> smem (tf32-rounded), own rows only
            #pragma unroll
            for (int nt = 0; nt < 8; nt++) {
                float2 pv;
                pv.x = tf32_round(s[nt][half*2 + 0]);
                pv.y = tf32_round(s[nt][half*2 + 1]);
                *(float2*)&Ps[(rbase + half*8)*FPP + nt*8 + 2*lm] = pv;
            }
        }
        __syncwarp();   // P written/read only within this warp's 16 rows

        // ---- O += P V ----
        #pragma unroll
        for (int ks = 0; ks < 8; ks++) {
            unsigned a[4];
            a[0] = __float_as_uint(Ps[(rbase    )*FPP + ks*8 + lm]);
            a[1] = __float_as_uint(Ps[(rbase + 8)*FPP + ks*8 + lm]);
            a[2] = __float_as_uint(Ps[(rbase    )*FPP + ks*8 + lm + 4]);
            a[3] = __float_as_uint(Ps[(rbase + 8)*FPP + ks*8 + lm + 4]);
            #pragma unroll
            for (int nt = 0; nt < 16; nt++) {
                unsigned b[2];
                b[0] = __float_as_uint(Vs[(ks*8 + lm    )*FVP + nt*8 + l4]);
                b[1] = __float_as_uint(Vs[(ks*8 + lm + 4)*FVP + nt*8 + l4]);
                mma_tf32(o[nt], a, b);
            }
        }
    }

    // ---- normalize + write g_ao as fp16 (input to the Wo GEMM) ----
    #pragma unroll
    for (int half = 0; half < 2; half++) {
        const float inv = 1.f / lrow[half];
        const int row = q0 + rbase + half * 8;
        __half* dst = g_ao + ((size_t)bh * SEQ + row) * HD;
        #pragma unroll
        for (int nt = 0; nt < 16; nt++) {
            __half2 hv = __floats2half2_rn(o[nt][half*2 + 0] * inv,
                                           o[nt][half*2 + 1] * inv);
            *(__half2*)&dst[nt*8 + 2*lm] = hv;
        }
    }
}

// ---------------------------------------------------------------------------
extern "C" void kernel_launch(void* const* d_in, const int* in_sizes, int n_in,
                              void* d_out, int out_size)
{
    const float4* x  = (const float4*)d_in[0];
    const float4* Wq = (const float4*)d_in[1];
    const float4* Wk = (const float4*)d_in[2];
    const float4* Wv = (const float4*)d_in[3];
    const float4* Wo = (const float4*)d_in[4];
    float* out = (float*)d_out;

    cudaFuncSetAttribute(flash_mma_kernel,
                         cudaFuncAttributeMaxDynamicSharedMemorySize, FL_SMEM);
    cudaFuncSetAttribute(gemm_mma<0>,
                         cudaFuncAttributeMaxDynamicSharedMemorySize, GEMM_SMEM);
    cudaFuncSetAttribute(gemm_mma<1>,
                         cudaFuncAttributeMaxDynamicSharedMemorySize, GEMM_SMEM);

    rope_table_kernel<<<(SEQ*(HD/2) + 255)/256, 256>>>();
    convert_x_kernel<<<((MROWS*HID)/4 + 255)/256, 256>>>(x);
    convert_w_kernel<<<(4*((HID*HID)/4) + 255)/256, 256>>>(Wq, Wk, Wv, Wo);

    // 4th launch -> profiler's sampled slot: finally get gemm_mma's profile
    gemm_mma<0><<<dim3(HID/128, MROWS/128, 3), 256, GEMM_SMEM>>>(nullptr);
    rope_apply_kernel<<<(BATCHN*NH*SEQ*(HD/2) + 255)/256, 256>>>();
    flash_mma_kernel<<<dim3(SEQ/128, BATCHN*NH), 256, FL_SMEM>>>();
    gemm_mma<1><<<dim3(HID/128, MROWS/128, 1), 256, GEMM_SMEM>>>(out);
}